// round 6
// baseline (speedup 1.0000x reference)
#include <cuda_runtime.h>
#include <cstdint>

// Problem constants (fixed by setup_inputs)
#define C_    32
#define S_    9
#define H_    192
#define W_    256
#define G_    8
#define NSRC  8            // N-1 source images
#define TW    16           // pixels (w) per block tile
#define THREADS 256

#define WS    (W_*S_)      // 2304
#define HWS   (H_*WS)      // 442368
#define CHWS  (C_*HWS)     // 14155776
#define ROW   (TW*S_)      // 144 data floats per channel row
#define F4ROW (ROW/4)      // 36 float4 per channel row
#define TILE_F4 (C_*F4ROW) // 1152 float4 per image tile
#define ROWP  152          // padded src row stride: halves on disjoint bank sets
#define ROWR  144          // ref row stride (prologue-only access)

#define REF_FLOATS (C_*ROWR)           // 4608
#define TILEP      (C_*ROWP)           // 4864
#define OFF_REF   0
#define OFF_SRC0  (REF_FLOATS)                 // 4608
#define OFF_SRC1  (OFF_SRC0+TILEP)             // 9472
#define OFF_SRC2  (OFF_SRC1+TILEP)             // 14336
// prologue scratch overlays src2 (src2 staged only after prologue)
#define OFF_WPT   OFF_SRC2                     // 1024: WpT[c*32+d]
#define OFF_BP    (OFF_WPT+1024)
#define OFF_PC4   (OFF_BP+32)                  // 512: pc4[d*16+w]
#define OFF_U     (OFF_PC4+512)                // 512: u[c*16+w]
#define OFF_ATT   (OFF_U+512)                  // 144: att[w*9+s]
#define SMEM_FLOATS (OFF_SRC2+TILEP)           // 19200
#define SMEM_BYTES  (SMEM_FLOATS*4)            // 76800 -> 3 blocks/SM

__device__ __forceinline__ void cp16(float* dst, const float4* src) {
    uint32_t s = (uint32_t)__cvta_generic_to_shared(dst);
    asm volatile("cp.async.cg.shared.global [%0], [%1], 16;\n" :: "r"(s), "l"(src));
}
__device__ __forceinline__ void cp_commit() { asm volatile("cp.async.commit_group;\n" ::); }
__device__ __forceinline__ void cp_wait2()  { asm volatile("cp.async.wait_group 2;\n" ::); }
__device__ __forceinline__ void cp_wait1()  { asm volatile("cp.async.wait_group 1;\n" ::); }
__device__ __forceinline__ void cp_wait0()  { asm volatile("cp.async.wait_group 0;\n" ::); }

// Stage one image tile: 1152 float4 = 4*256 + 128 (tail). All threads commit.
template<int ROWSTRIDE>
__device__ __forceinline__ void stage_tile(float* dst, const float4* gbase) {
    #pragma unroll
    for (int i = 0; i < 4; i++) {
        int j = threadIdx.x + i * THREADS;   // 0..1023
        int c = j / F4ROW;
        int k = j - c * F4ROW;
        cp16(dst + c * ROWSTRIDE + k * 4, gbase + (size_t)c * (HWS >> 2) + k);
    }
    if (threadIdx.x < (TILE_F4 - 4 * THREADS)) {   // last 128 float4
        int j = threadIdx.x + 4 * THREADS;          // 1024..1151
        int c = j / F4ROW;
        int k = j - c * F4ROW;
        cp16(dst + c * ROWSTRIDE + k * 4, gbase + (size_t)c * (HWS >> 2) + k);
    }
    cp_commit();
}

__global__ __launch_bounds__(THREADS)
void gcfs_kernel(const float* __restrict__ f,
                 const float* __restrict__ Wp,
                 const float* __restrict__ bp,
                 float* __restrict__ out) {
    extern __shared__ float sm[];
    float* refS = sm + OFF_REF;
    float* WpT  = sm + OFF_WPT;
    float* bpS  = sm + OFF_BP;
    float* pc4  = sm + OFF_PC4;
    float* uS   = sm + OFF_U;
    float* attS = sm + OFF_ATT;

    const int t  = threadIdx.x;
    const int h  = blockIdx.y;
    const int w0 = blockIdx.x * TW;

    const float4* fb4 = (const float4*)f;
    const size_t tile4 = ((size_t)h * WS + (size_t)w0 * S_) >> 2;

    // --- prologue staging: ref (g0), src0 (g1), src1 (g2) ---
    stage_tile<ROWR>(refS,          fb4 + tile4);
    stage_tile<ROWP>(sm + OFF_SRC0, fb4 + (size_t)1*(CHWS>>2) + tile4);
    stage_tile<ROWP>(sm + OFF_SRC1, fb4 + (size_t)2*(CHWS>>2) + tile4);

    // Wp (transposed) + bp into scratch (overlays src2)
    for (int i = t; i < C_ * C_; i += THREADS) {
        int d = i >> 5, c = i & 31;
        WpT[c * 32 + d] = Wp[i];
    }
    if (t < C_) bpS[t] = bp[t];

    cp_wait2();          // ref complete; src0/src1 still streaming
    __syncthreads();

    // --- pc4[d][w] = sum_c Wp[d,c]*ref[c,w,4] + bp[d]  (512 items) ---
    #pragma unroll
    for (int i = 0; i < 2; i++) {
        int item = t + i * THREADS;
        int w = item & 15, d = item >> 4;
        float acc = bpS[d];
        #pragma unroll
        for (int c = 0; c < C_; c++)
            acc += WpT[c * 32 + d] * refS[c * ROWR + w * S_ + 4];
        pc4[d * 16 + w] = acc;
    }
    __syncthreads();

    // --- u[c][w] = sum_d pc4[d][w]*Wp[d,c] ---
    #pragma unroll
    for (int i = 0; i < 2; i++) {
        int item = t + i * THREADS;
        int w = item & 15, c = item >> 4;
        float acc = 0.f;
        #pragma unroll
        for (int d = 0; d < C_; d++)
            acc += pc4[d * 16 + w] * WpT[c * 32 + d];
        uS[c * 16 + w] = acc;
    }
    __syncthreads();

    // --- logits + softmax (16 lanes; one pixel per lane) ---
    if (t < TW) {
        const int w = t;
        float v = 0.f;
        #pragma unroll
        for (int d = 0; d < C_; d++) v += pc4[d * 16 + w] * bpS[d];

        float lg[S_];
        #pragma unroll
        for (int s = 0; s < S_; s++) {
            float a = v;
            #pragma unroll
            for (int c = 0; c < C_; c++)
                a += uS[c * 16 + w] * refS[c * ROWR + w * S_ + s];
            lg[s] = a * 0.17677669529663687f;   // 1/sqrt(32)
        }
        float mx = lg[0];
        #pragma unroll
        for (int s = 1; s < S_; s++) mx = fmaxf(mx, lg[s]);
        float sum = 0.f;
        #pragma unroll
        for (int s = 0; s < S_; s++) { lg[s] = expf(lg[s] - mx); sum += lg[s]; }
        float inv = 1.f / sum;
        #pragma unroll
        for (int s = 0; s < S_; s++) attS[w * S_ + s] = lg[s] * inv;
    }
    __syncthreads();

    // --- mapping: w = t&15, p = (t>>4)&1, g = t>>5 ---
    // thread owns channels g*4 + p*2 + {0,1}; partner (shfl xor 16) has the other pair
    const int w = t & 15;
    const int p = (t >> 4) & 1;
    const int g = t >> 5;
    const int c0 = g * 4 + p * 2;

    float rw[2][S_];
    #pragma unroll
    for (int c = 0; c < 2; c++) {
        #pragma unroll
        for (int s = 0; s < S_; s++)
            rw[c][s] = refS[(c0 + c) * ROWR + w * S_ + s] * attS[w * S_ + s];
    }
    __syncthreads();     // scratch reads done before src2 overwrites it

    // stage src2 (group 3) into former scratch region
    stage_tile<ROWP>(sm + OFF_SRC2, fb4 + (size_t)3*(CHWS>>2) + tile4);

    // --- main loop: depth-3 ring, block-synchronized ---
    float* const bufs[3] = { sm + OFF_SRC0, sm + OFF_SRC1, sm + OFF_SRC2 };
    const size_t outBase = (size_t)h * W_ + w0 + w;

    #pragma unroll 1
    for (int n = 0; n < NSRC; n++) {
        // groups: ref=0, srcN=N+1 (N<=2), refills at iter 0..4 = groups 4..8.
        // need group n+1 complete; pending after that = 2 for n<=5, 1 at n=6, 0 at n=7
        if (n <= 5) cp_wait2();
        else if (n == 6) cp_wait1();
        else cp_wait0();
        __syncthreads();             // staged data visible to all warps

        const float* sb = bufs[n % 3] + c0 * ROWP + w * S_;
        float acc = 0.f;
        #pragma unroll
        for (int c = 0; c < 2; c++) {
            #pragma unroll
            for (int s = 0; s < S_; s++)
                acc += rw[c][s] * sb[c * ROWP + s];
        }
        acc += __shfl_xor_sync(0xFFFFFFFFu, acc, 16);
        if (p == 0)
            out[((size_t)(n * G_ + g)) * (H_ * W_) + outBase] = acc;

        __syncthreads();             // all reads of buffer done before refill
        if (n <= 4)
            stage_tile<ROWP>(bufs[n % 3], fb4 + (size_t)(n + 4)*(CHWS>>2) + tile4);
    }
}

extern "C" void kernel_launch(void* const* d_in, const int* in_sizes, int n_in,
                              void* d_out, int out_size) {
    const float* f  = (const float*)d_in[0];
    const float* Wp = (const float*)d_in[1];
    const float* bp = (const float*)d_in[2];
    float* out = (float*)d_out;

    cudaFuncSetAttribute(gcfs_kernel,
                         cudaFuncAttributeMaxDynamicSharedMemorySize, SMEM_BYTES);
    dim3 grid(W_ / TW, H_);
    gcfs_kernel<<<grid, THREADS, SMEM_BYTES>>>(f, Wp, bp, out);
}